// round 1
// baseline (speedup 1.0000x reference)
#include <cuda_runtime.h>
#include <cstdint>

#define TOKENS 16384
#define HIDDEN 4096
#define NB 8
#define BLK 512

#define BM 128
#define BN 128
#define BK 16
#define THREADS 256
#define KITERS (BLK / BK)   // 32

#define AS_STRIDE 20    // BK + 4 pad -> conflict-free A fragment loads
#define BS_STRIDE 136   // BN + 8 pad -> conflict-free B fragment loads

__device__ __forceinline__ uint32_t f2tf32(float f) {
    uint32_t r;
    asm("cvt.rna.tf32.f32 %0, %1;" : "=r"(r) : "f"(f));
    return r;
}

__device__ __forceinline__ void mma_tf32(float c[4], uint32_t a0, uint32_t a1,
                                         uint32_t a2, uint32_t a3,
                                         uint32_t b0, uint32_t b1) {
    asm volatile(
        "mma.sync.aligned.m16n8k8.row.col.f32.tf32.tf32.f32 "
        "{%0,%1,%2,%3}, {%4,%5,%6,%7}, {%8,%9}, {%0,%1,%2,%3};\n"
        : "+f"(c[0]), "+f"(c[1]), "+f"(c[2]), "+f"(c[3])
        : "r"(a0), "r"(a1), "r"(a2), "r"(a3), "r"(b0), "r"(b1));
}

__global__ void __launch_bounds__(THREADS, 2)
tp_trans_kernel(const float* __restrict__ X,
                const float* __restrict__ W,
                float* __restrict__ O)
{
    __shared__ uint32_t As[2][BM * AS_STRIDE];   // 2 * 10240 B
    __shared__ uint32_t Bs[2][BK * BS_STRIDE];   // 2 *  8704 B

    const int t    = threadIdx.x;
    const int lane = t & 31;
    const int wid  = t >> 5;
    const int warp_m = wid & 1;     // 0..1  -> m offset 0/64
    const int warp_n = wid >> 1;    // 0..3  -> n offset 0/32/64/96

    const int bx = blockIdx.x;      // M tile (128)
    const int by = blockIdx.y;      // N tile within block (4)
    const int bz = blockIdx.z;      // which 512x512 block (8)

    const int m_base = bx * BM;
    const int n_base = by * BN;     // within the 512-wide block

    // ---- copy index setup ----
    // A: thread t -> row = t/2 (0..127), half = t&1 -> k offset half*8, two float4
    const int a_row  = t >> 1;
    const int a_half = t & 1;
    const float* Ag = X + (size_t)(m_base + a_row) * HIDDEN
                        + (size_t)bz * BLK + a_half * 8;
    uint32_t* const a_dst_base = (uint32_t*)0; (void)a_dst_base;
    const int a_soff = a_row * AS_STRIDE + a_half * 8;

    // B: thread t -> k row = t/16 (0..15), n4 = (t&15)*4, two float4 (n and n+64)
    const int b_kr = t >> 4;
    const int b_n  = (t & 15) * 4;
    const float* Bg = W + (size_t)bz * BLK * BLK + (size_t)b_kr * BLK
                        + n_base + b_n;
    const int b_soff = b_kr * BS_STRIDE + b_n;

    float acc[4][4][4];
#pragma unroll
    for (int i = 0; i < 4; i++)
#pragma unroll
        for (int j = 0; j < 4; j++)
#pragma unroll
            for (int r = 0; r < 4; r++) acc[i][j][r] = 0.0f;

    // ---- prologue: stage 0 ----
    float4 ra0 = *(const float4*)(Ag);
    float4 ra1 = *(const float4*)(Ag + 4);
    float4 rb0 = *(const float4*)(Bg);
    float4 rb1 = *(const float4*)(Bg + 64);
    {
        uint4 u0 = { f2tf32(ra0.x), f2tf32(ra0.y), f2tf32(ra0.z), f2tf32(ra0.w) };
        uint4 u1 = { f2tf32(ra1.x), f2tf32(ra1.y), f2tf32(ra1.z), f2tf32(ra1.w) };
        *(uint4*)(&As[0][a_soff])     = u0;
        *(uint4*)(&As[0][a_soff + 4]) = u1;
        uint4 v0 = { f2tf32(rb0.x), f2tf32(rb0.y), f2tf32(rb0.z), f2tf32(rb0.w) };
        uint4 v1 = { f2tf32(rb1.x), f2tf32(rb1.y), f2tf32(rb1.z), f2tf32(rb1.w) };
        *(uint4*)(&Bs[0][b_soff])      = v0;
        *(uint4*)(&Bs[0][b_soff + 64]) = v1;
    }
    __syncthreads();

    const int a_frag_col = lane & 3;        // k within 4
    const int a_frag_row = lane >> 2;       // m within 8
    const int m0w = warp_m * 64;
    const int n0w = warp_n * 32;

#pragma unroll 1
    for (int kt = 0; kt < KITERS; kt++) {
        // issue global loads for next stage early (latency hidden by compute)
        if (kt + 1 < KITERS) {
            const float* Agn = Ag + (kt + 1) * BK;
            const float* Bgn = Bg + (size_t)(kt + 1) * BK * BLK;
            ra0 = *(const float4*)(Agn);
            ra1 = *(const float4*)(Agn + 4);
            rb0 = *(const float4*)(Bgn);
            rb1 = *(const float4*)(Bgn + 64);
        }

        const int buf = kt & 1;
        const uint32_t* __restrict__ Asb = As[buf];
        const uint32_t* __restrict__ Bsb = Bs[buf];

#pragma unroll
        for (int kk = 0; kk < BK; kk += 8) {
            uint32_t af[4][4];
#pragma unroll
            for (int i = 0; i < 4; i++) {
                const uint32_t* p = Asb + (m0w + i * 16 + a_frag_row) * AS_STRIDE
                                        + kk + a_frag_col;
                af[i][0] = p[0];
                af[i][1] = p[8 * AS_STRIDE];
                af[i][2] = p[4];
                af[i][3] = p[8 * AS_STRIDE + 4];
            }
            uint32_t bf[4][2];
#pragma unroll
            for (int j = 0; j < 4; j++) {
                const uint32_t* p = Bsb + (kk + a_frag_col) * BS_STRIDE
                                        + n0w + j * 8 + a_frag_row;
                bf[j][0] = p[0];
                bf[j][1] = p[4 * BS_STRIDE];
            }
#pragma unroll
            for (int i = 0; i < 4; i++)
#pragma unroll
                for (int j = 0; j < 4; j++)
                    mma_tf32(acc[i][j], af[i][0], af[i][1], af[i][2], af[i][3],
                             bf[j][0], bf[j][1]);
        }

        if (kt + 1 < KITERS) {
            const int nbuf = (kt + 1) & 1;
            uint4 u0 = { f2tf32(ra0.x), f2tf32(ra0.y), f2tf32(ra0.z), f2tf32(ra0.w) };
            uint4 u1 = { f2tf32(ra1.x), f2tf32(ra1.y), f2tf32(ra1.z), f2tf32(ra1.w) };
            *(uint4*)(&As[nbuf][a_soff])     = u0;
            *(uint4*)(&As[nbuf][a_soff + 4]) = u1;
            uint4 v0 = { f2tf32(rb0.x), f2tf32(rb0.y), f2tf32(rb0.z), f2tf32(rb0.w) };
            uint4 v1 = { f2tf32(rb1.x), f2tf32(rb1.y), f2tf32(rb1.z), f2tf32(rb1.w) };
            *(uint4*)(&Bs[nbuf][b_soff])      = v0;
            *(uint4*)(&Bs[nbuf][b_soff + 64]) = v1;
        }
        __syncthreads();
    }

    // ---- epilogue: c0:(r, 2c) c1:(r, 2c+1) c2:(r+8, 2c) c3:(r+8, 2c+1) ----
    const int orow = m_base + m0w + (lane >> 2);
    const int ocol = bz * BLK + n_base + n0w + (lane & 3) * 2;
#pragma unroll
    for (int i = 0; i < 4; i++) {
#pragma unroll
        for (int j = 0; j < 4; j++) {
            float2 v0 = make_float2(acc[i][j][0], acc[i][j][1]);
            float2 v1 = make_float2(acc[i][j][2], acc[i][j][3]);
            *(float2*)(O + (size_t)(orow + i * 16)     * HIDDEN + ocol + j * 8) = v0;
            *(float2*)(O + (size_t)(orow + i * 16 + 8) * HIDDEN + ocol + j * 8) = v1;
        }
    }
}

extern "C" void kernel_launch(void* const* d_in, const int* in_sizes, int n_in,
                              void* d_out, int out_size)
{
    const float* x      = (const float*)d_in[0];
    const float* blocks = (const float*)d_in[1];
    float* out          = (float*)d_out;
    (void)in_sizes; (void)n_in; (void)out_size;

    dim3 grid(TOKENS / BM, BLK / BN, NB);   // (128, 4, 8)
    tp_trans_kernel<<<grid, THREADS>>>(x, blocks, out);
}

// round 8
// speedup vs baseline: 1.2086x; 1.2086x over previous
#include <cuda_runtime.h>
#include <cuda_fp16.h>
#include <cstdint>

#define TOKENS 16384
#define HIDDEN 4096
#define NB 8
#define BLK 512

#define BM 128
#define BN 128
#define BK 32                  // k halfs per stage (64B rows)
#define NSTAGE (BLK / BK)      // 16
#define RING 4
#define THREADS 256

#define A_STAGE_BYTES (BM * BK * 2)   // 8192
#define B_STAGE_BYTES (BN * BK * 2)   // 8192
#define SMEM_A 0
#define SMEM_B (RING * A_STAGE_BYTES)              // 32768
#define SMEM_TOTAL (SMEM_B + RING * B_STAGE_BYTES) // 65536

__device__ __half g_Wt[NB * BLK * BLK];   // W transposed to [n][k], fp16

__device__ __forceinline__ uint32_t smem_u32(const void* p) {
    uint32_t a;
    asm("{ .reg .u64 t; cvta.to.shared.u64 t, %1; cvt.u32.u64 %0, t; }" : "=r"(a) : "l"(p));
    return a;
}
__device__ __forceinline__ void ldm4(uint32_t& r0, uint32_t& r1, uint32_t& r2,
                                     uint32_t& r3, uint32_t addr) {
    asm volatile("ldmatrix.sync.aligned.m8n8.x4.shared.b16 {%0,%1,%2,%3}, [%4];"
                 : "=r"(r0), "=r"(r1), "=r"(r2), "=r"(r3) : "r"(addr));
}
__device__ __forceinline__ void mma_f16(float c[4], uint32_t a0, uint32_t a1,
                                        uint32_t a2, uint32_t a3,
                                        uint32_t b0, uint32_t b1) {
    asm volatile(
        "mma.sync.aligned.m16n8k16.row.col.f32.f16.f16.f32 "
        "{%0,%1,%2,%3}, {%4,%5,%6,%7}, {%8,%9}, {%0,%1,%2,%3};\n"
        : "+f"(c[0]), "+f"(c[1]), "+f"(c[2]), "+f"(c[3])
        : "r"(a0), "r"(a1), "r"(a2), "r"(a3), "r"(b0), "r"(b1));
}
__device__ __forceinline__ void cp16(uint32_t dst, const void* src) {
    asm volatile("cp.async.cg.shared.global [%0], [%1], 16;" :: "r"(dst), "l"(src) : "memory");
}
#define CP_COMMIT() asm volatile("cp.async.commit_group;" ::: "memory")
#define CP_WAIT2()  asm volatile("cp.async.wait_group 2;" ::: "memory")

__global__ void transpose_half_kernel(const float* __restrict__ W) {
    __shared__ float t[32][33];
    const int z = blockIdx.z;
    const int k0 = blockIdx.x * 32, n0 = blockIdx.y * 32;
    const float* Wz = W + (size_t)z * BLK * BLK;
    __half* Wtz = g_Wt + (size_t)z * BLK * BLK;
    const int tx = threadIdx.x, ty = threadIdx.y;
#pragma unroll
    for (int i = 0; i < 32; i += 8)
        t[ty + i][tx] = Wz[(size_t)(k0 + ty + i) * BLK + n0 + tx];
    __syncthreads();
#pragma unroll
    for (int i = 0; i < 32; i += 8)
        Wtz[(size_t)(n0 + ty + i) * BLK + k0 + tx] = __float2half_rn(t[tx][ty + i]);
}

__global__ void __launch_bounds__(THREADS, 2)
tp_fp16_kernel(const float* __restrict__ X, float* __restrict__ O)
{
    extern __shared__ char smem[];
    const uint32_t sb = smem_u32(smem);
    const int tid  = threadIdx.x;
    const int lane = tid & 31;
    const int wid  = tid >> 5;
    const int m0w  = (wid & 1) * 64;
    const int n0w  = (wid >> 1) * 32;

    const int m_base = blockIdx.x * BM;
    const int n_base = blockIdx.y * BN;
    const int bz     = blockIdx.z;

    // staging plan: thread t -> row t&127, k-half cp2 = t>>7 (two 16B chunks)
    const int s_row = tid & 127;
    const int s_cp2 = tid >> 7;
    const int s_xr  = (s_row >> 1) & 3;
    const uint32_t sts0 = (uint32_t)s_row * 64 + (uint32_t)((2 * s_cp2 + 0) ^ s_xr) * 16;
    const uint32_t sts1 = (uint32_t)s_row * 64 + (uint32_t)((2 * s_cp2 + 1) ^ s_xr) * 16;
    const float*  Ag = X + (size_t)(m_base + s_row) * HIDDEN + (size_t)bz * BLK + s_cp2 * 16;
    const __half* Bg = g_Wt + (size_t)bz * BLK * BLK
                            + (size_t)(n_base + s_row) * BLK + s_cp2 * 16;

    // ldmatrix addresses
    const int a_fr = lane & 15;
    const int a_cs = lane >> 4;
    const int a_xr = (a_fr >> 1) & 3;
    const uint32_t a_lm_base = (uint32_t)(m0w + a_fr) * 64 + (uint32_t)(a_cs ^ a_xr) * 16;
    const int b_nr = (lane & 7) + ((lane >> 4) & 1) * 8;
    const int b_cs = (lane >> 3) & 1;
    const int b_xr = ((lane & 7) >> 1) & 3;
    const uint32_t b_lm_base = (uint32_t)(n0w + b_nr) * 64 + (uint32_t)(b_cs ^ b_xr) * 16;

    float acc[4][4][4];
#pragma unroll
    for (int i = 0; i < 4; i++)
#pragma unroll
        for (int j = 0; j < 4; j++)
#pragma unroll
            for (int r = 0; r < 4; r++) acc[i][j][r] = 0.0f;

    // ---- prologue: B stages 0..2 (cp.async), A stages 0..1 (LDG+cvt+STS) ----
#pragma unroll
    for (int q = 0; q < 3; q++) {
        uint32_t bb = sb + SMEM_B + q * B_STAGE_BYTES;
        cp16(bb + sts0, Bg + q * BK + 0);
        cp16(bb + sts1, Bg + q * BK + 8);
        CP_COMMIT();
    }
#pragma unroll
    for (int q = 0; q < 2; q++) {
        float4 f0 = *(const float4*)(Ag + q * BK + 0);
        float4 f1 = *(const float4*)(Ag + q * BK + 4);
        float4 f2 = *(const float4*)(Ag + q * BK + 8);
        float4 f3 = *(const float4*)(Ag + q * BK + 12);
        __half2 h[8];
        h[0] = __floats2half2_rn(f0.x, f0.y); h[1] = __floats2half2_rn(f0.z, f0.w);
        h[2] = __floats2half2_rn(f1.x, f1.y); h[3] = __floats2half2_rn(f1.z, f1.w);
        h[4] = __floats2half2_rn(f2.x, f2.y); h[5] = __floats2half2_rn(f2.z, f2.w);
        h[6] = __floats2half2_rn(f3.x, f3.y); h[7] = __floats2half2_rn(f3.z, f3.w);
        uint32_t* hp = (uint32_t*)h;
        char* ab = smem + SMEM_A + q * A_STAGE_BYTES;
        *(uint4*)(ab + sts0) = make_uint4(hp[0], hp[1], hp[2], hp[3]);
        *(uint4*)(ab + sts1) = make_uint4(hp[4], hp[5], hp[6], hp[7]);
    }

    // ---- main loop ----
#pragma unroll 1
    for (int c = 0; c < NSTAGE; c++) {
        CP_WAIT2();
        __syncthreads();

        if (c + 3 < NSTAGE) {
            uint32_t bb = sb + SMEM_B + ((c + 3) & 3) * B_STAGE_BYTES;
            cp16(bb + sts0, Bg + (c + 3) * BK + 0);
            cp16(bb + sts1, Bg + (c + 3) * BK + 8);
        }
        CP_COMMIT();

        float4 f0, f1, f2, f3;
        if (c + 2 < NSTAGE) {
            const float* Agn = Ag + (c + 2) * BK;
            f0 = *(const float4*)(Agn + 0);
            f1 = *(const float4*)(Agn + 4);
            f2 = *(const float4*)(Agn + 8);
            f3 = *(const float4*)(Agn + 12);
        }

        const uint32_t Ab = sb + SMEM_A + (c & 3) * A_STAGE_BYTES;
        const uint32_t Bb = sb + SMEM_B + (c & 3) * B_STAGE_BYTES;
#pragma unroll
        for (int kk = 0; kk < 2; kk++) {
            const uint32_t kofs = (uint32_t)kk << 5;
            uint32_t a[4][4];
#pragma unroll
            for (int i = 0; i < 4; i++)
                ldm4(a[i][0], a[i][1], a[i][2], a[i][3],
                     Ab + (a_lm_base ^ kofs) + i * 1024);
            uint32_t b[2][4];
#pragma unroll
            for (int j = 0; j < 2; j++)
                ldm4(b[j][0], b[j][1], b[j][2], b[j][3],
                     Bb + (b_lm_base ^ kofs) + j * 1024);
#pragma unroll
            for (int i = 0; i < 4; i++)
#pragma unroll
                for (int jj = 0; jj < 4; jj++)
                    mma_f16(acc[i][jj], a[i][0], a[i][1], a[i][2], a[i][3],
                            b[jj >> 1][(jj & 1) * 2], b[jj >> 1][(jj & 1) * 2 + 1]);
        }

        if (c + 2 < NSTAGE) {
            __half2 h[8];
            h[0] = __floats2half2_rn(f0.x, f0.y); h[1] = __floats2half2_rn(f0.z, f0.w);
            h[2] = __floats2half2_rn(f1.x, f1.y); h[3] = __floats2half2_rn(f1.z, f1.w);
            h[4] = __floats2half2_rn(f2.x, f2.y); h[5] = __floats2half2_rn(f2.z, f2.w);
            h[6] = __floats2half2_rn(f3.x, f3.y); h[7] = __floats2half2_rn(f3.z, f3.w);
            uint32_t* hp = (uint32_t*)h;
            char* ab = smem + SMEM_A + ((c + 2) & 3) * A_STAGE_BYTES;
            *(uint4*)(ab + sts0) = make_uint4(hp[0], hp[1], hp[2], hp[3]);
            *(uint4*)(ab + sts1) = make_uint4(hp[4], hp[5], hp[6], hp[7]);
        }
    }

    // ---- epilogue ----
    const int orow = m_base + m0w + (lane >> 2);
    const int ocol = bz * BLK + n_base + n0w + (lane & 3) * 2;
#pragma unroll
    for (int i = 0; i < 4; i++) {
#pragma unroll
        for (int jj = 0; jj < 4; jj++) {
            float2 v0 = make_float2(acc[i][jj][0], acc[i][jj][1]);
            float2 v1 = make_float2(acc[i][jj][2], acc[i][jj][3]);
            *(float2*)(O + (size_t)(orow + i * 16)     * HIDDEN + ocol + jj * 8) = v0;
            *(float2*)(O + (size_t)(orow + i * 16 + 8) * HIDDEN + ocol + jj * 8) = v1;
        }
    }
}

extern "C" void kernel_launch(void* const* d_in, const int* in_sizes, int n_in,
                              void* d_out, int out_size)
{
    const float* x = (const float*)d_in[0];
    const float* w = (const float*)d_in[1];
    float* out = (float*)d_out;
    (void)in_sizes; (void)n_in; (void)out_size;

    cudaFuncSetAttribute(tp_fp16_kernel,
                         cudaFuncAttributeMaxDynamicSharedMemorySize, SMEM_TOTAL);

    transpose_half_kernel<<<dim3(BLK / 32, BLK / 32, NB), dim3(32, 8)>>>(w);
    tp_fp16_kernel<<<dim3(TOKENS / BM, BLK / BN, NB), THREADS, SMEM_TOTAL>>>(x, out);
}

// round 9
// speedup vs baseline: 2.2259x; 1.8417x over previous
#include <cuda_runtime.h>
#include <cuda_fp16.h>
#include <cstdint>

#define TOKENS 16384
#define HIDDEN 4096
#define NB 8
#define BLK 512

#define BM 128
#define BN 128
#define BK 64                  // k halfs per stage -> 128B smem rows
#define NSTAGE (BLK / BK)      // 8
#define RING 3
#define THREADS 256

#define STAGE_BYTES (128 * 128)                    // 16384
#define SMEM_A 0
#define SMEM_B (RING * STAGE_BYTES)                // 49152
#define SMEM_TOTAL (SMEM_B + RING * STAGE_BYTES)   // 98304

__device__ __half g_Wt[NB * BLK * BLK];            // W transposed to [n][k], fp16
__device__ __half g_Xh[(size_t)TOKENS * HIDDEN];   // X converted to fp16

__device__ __forceinline__ uint32_t smem_u32(const void* p) {
    uint32_t a;
    asm("{ .reg .u64 t; cvta.to.shared.u64 t, %1; cvt.u32.u64 %0, t; }" : "=r"(a) : "l"(p));
    return a;
}
__device__ __forceinline__ void ldm4(uint32_t& r0, uint32_t& r1, uint32_t& r2,
                                     uint32_t& r3, uint32_t addr) {
    asm volatile("ldmatrix.sync.aligned.m8n8.x4.shared.b16 {%0,%1,%2,%3}, [%4];"
                 : "=r"(r0), "=r"(r1), "=r"(r2), "=r"(r3) : "r"(addr));
}
__device__ __forceinline__ void mma_f16(float c[4], uint32_t a0, uint32_t a1,
                                        uint32_t a2, uint32_t a3,
                                        uint32_t b0, uint32_t b1) {
    asm volatile(
        "mma.sync.aligned.m16n8k16.row.col.f32.f16.f16.f32 "
        "{%0,%1,%2,%3}, {%4,%5,%6,%7}, {%8,%9}, {%0,%1,%2,%3};\n"
        : "+f"(c[0]), "+f"(c[1]), "+f"(c[2]), "+f"(c[3])
        : "r"(a0), "r"(a1), "r"(a2), "r"(a3), "r"(b0), "r"(b1));
}
__device__ __forceinline__ void cp16(uint32_t dst, const void* src) {
    asm volatile("cp.async.cg.shared.global [%0], [%1], 16;" :: "r"(dst), "l"(src) : "memory");
}
#define CP_COMMIT() asm volatile("cp.async.commit_group;" ::: "memory")
#define CP_WAIT1()  asm volatile("cp.async.wait_group 1;" ::: "memory")

// ---------------- prepass 1: X fp32 -> fp16 ----------------
__global__ void __launch_bounds__(256)
convert_x_kernel(const float* __restrict__ X) {
    size_t t = (size_t)blockIdx.x * blockDim.x + threadIdx.x;   // 0 .. 8M-1
    const float4* src = (const float4*)X;
    float4 f0 = src[2 * t];
    float4 f1 = src[2 * t + 1];
    __half2 h0 = __floats2half2_rn(f0.x, f0.y);
    __half2 h1 = __floats2half2_rn(f0.z, f0.w);
    __half2 h2 = __floats2half2_rn(f1.x, f1.y);
    __half2 h3 = __floats2half2_rn(f1.z, f1.w);
    uint4 v = make_uint4(*(uint32_t*)&h0, *(uint32_t*)&h1,
                         *(uint32_t*)&h2, *(uint32_t*)&h3);
    ((uint4*)g_Xh)[t] = v;
}

// ---------------- prepass 2: W transpose + fp16 ----------------
__global__ void transpose_half_kernel(const float* __restrict__ W) {
    __shared__ float t[32][33];
    const int z = blockIdx.z;
    const int k0 = blockIdx.x * 32, n0 = blockIdx.y * 32;
    const float* Wz = W + (size_t)z * BLK * BLK;
    __half* Wtz = g_Wt + (size_t)z * BLK * BLK;
    const int tx = threadIdx.x, ty = threadIdx.y;
#pragma unroll
    for (int i = 0; i < 32; i += 8)
        t[ty + i][tx] = Wz[(size_t)(k0 + ty + i) * BLK + n0 + tx];
    __syncthreads();
#pragma unroll
    for (int i = 0; i < 32; i += 8)
        Wtz[(size_t)(n0 + ty + i) * BLK + k0 + tx] = __float2half_rn(t[tx][ty + i]);
}

// ---------------- main kernel ----------------
__global__ void __launch_bounds__(THREADS, 2)
tp_fp16_kernel(float* __restrict__ O)
{
    extern __shared__ char smem[];
    const uint32_t sb = smem_u32(smem);
    const int tid  = threadIdx.x;
    const int lane = tid & 31;
    const int wid  = tid >> 5;
    const int m0w  = (wid & 1) * 64;
    const int n0w  = (wid >> 1) * 32;

    const int m_base = blockIdx.x * BM;
    const int n_base = blockIdx.y * BN;
    const int bz     = blockIdx.z;

    // ---- cp.async staging plan: thread -> 4 rows (cp_r + 32i), one 16B chunk each ----
    const int cp_r = tid >> 3;          // 0..31
    const int cp_c = tid & 7;           // chunk 0..7
    const uint32_t cp_sw = (uint32_t)((cp_c ^ (cp_r & 7)) * 16);
    const uint32_t cp_so = (uint32_t)cp_r * 128 + cp_sw;
    const __half* Axg = g_Xh + (size_t)(m_base + cp_r) * HIDDEN + (size_t)bz * BLK + cp_c * 8;
    const __half* Bxg = g_Wt + (size_t)bz * BLK * BLK + (size_t)(n_base + cp_r) * BLK + cp_c * 8;

    // ---- ldmatrix addressing ----
    // A: x4 -> m0-7/k0-7, m8-15/k0-7, m0-7/k8-15, m8-15/k8-15
    const int a_R  = m0w + (lane & 15);
    const int a_cs = lane >> 4;                 // k-chunk half
    const int a_swr = a_R & 7;
    const uint32_t a_rb = (uint32_t)a_R * 128;
    // B: x4 -> n0-7/k0-7, n0-7/k8-15, n8-15/k0-7, n8-15/k8-15
    const int b_N  = n0w + (lane & 7) + ((lane >> 4) & 1) * 8;
    const int b_cs = (lane >> 3) & 1;
    const int b_swr = b_N & 7;
    const uint32_t b_rb = (uint32_t)b_N * 128;

    float acc[4][4][4];
#pragma unroll
    for (int i = 0; i < 4; i++)
#pragma unroll
        for (int j = 0; j < 4; j++)
#pragma unroll
            for (int r = 0; r < 4; r++) acc[i][j][r] = 0.0f;

    // ---- prologue: stages 0,1 ----
#pragma unroll
    for (int q = 0; q < 2; q++) {
        uint32_t ab = sb + SMEM_A + q * STAGE_BYTES + cp_so;
        uint32_t bb = sb + SMEM_B + q * STAGE_BYTES + cp_so;
#pragma unroll
        for (int i = 0; i < 4; i++) {
            cp16(ab + i * 32 * 128, Axg + (size_t)i * 32 * HIDDEN + q * BK);
            cp16(bb + i * 32 * 128, Bxg + (size_t)i * 32 * BLK + q * BK);
        }
        CP_COMMIT();
    }

    // ---- main loop: 8 bodies ----
#pragma unroll 1
    for (int c = 0; c < NSTAGE; c++) {
        CP_WAIT1();
        __syncthreads();

        if (c + 2 < NSTAGE) {
            const int sl = (c + 2) % RING;
            uint32_t ab = sb + SMEM_A + sl * STAGE_BYTES + cp_so;
            uint32_t bb = sb + SMEM_B + sl * STAGE_BYTES + cp_so;
#pragma unroll
            for (int i = 0; i < 4; i++) {
                cp16(ab + i * 32 * 128, Axg + (size_t)i * 32 * HIDDEN + (c + 2) * BK);
                cp16(bb + i * 32 * 128, Bxg + (size_t)i * 32 * BLK + (c + 2) * BK);
            }
        }
        CP_COMMIT();

        const uint32_t Ab = sb + SMEM_A + (c % RING) * STAGE_BYTES;
        const uint32_t Bb = sb + SMEM_B + (c % RING) * STAGE_BYTES;
#pragma unroll
        for (int kk = 0; kk < 4; kk++) {
            uint32_t a[4][4];
#pragma unroll
            for (int i = 0; i < 4; i++)
                ldm4(a[i][0], a[i][1], a[i][2], a[i][3],
                     Ab + a_rb + (uint32_t)i * 2048
                        + (uint32_t)(((2 * kk + a_cs) ^ a_swr) * 16));
            uint32_t b[2][4];
#pragma unroll
            for (int j = 0; j < 2; j++)
                ldm4(b[j][0], b[j][1], b[j][2], b[j][3],
                     Bb + b_rb + (uint32_t)j * 2048
                        + (uint32_t)(((2 * kk + b_cs) ^ b_swr) * 16));
#pragma unroll
            for (int i = 0; i < 4; i++)
#pragma unroll
                for (int jj = 0; jj < 4; jj++)
                    mma_f16(acc[i][jj], a[i][0], a[i][1], a[i][2], a[i][3],
                            b[jj >> 1][(jj & 1) * 2], b[jj >> 1][(jj & 1) * 2 + 1]);
        }
    }

    // ---- epilogue ----
    const int orow = m_base + m0w + (lane >> 2);
    const int ocol = bz * BLK + n_base + n0w + (lane & 3) * 2;
#pragma unroll
    for (int i = 0; i < 4; i++) {
#pragma unroll
        for (int jj = 0; jj < 4; jj++) {
            float2 v0 = make_float2(acc[i][jj][0], acc[i][jj][1]);
            float2 v1 = make_float2(acc[i][jj][2], acc[i][jj][3]);
            *(float2*)(O + (size_t)(orow + i * 16)     * HIDDEN + ocol + jj * 8) = v0;
            *(float2*)(O + (size_t)(orow + i * 16 + 8) * HIDDEN + ocol + jj * 8) = v1;
        }
    }
}

extern "C" void kernel_launch(void* const* d_in, const int* in_sizes, int n_in,
                              void* d_out, int out_size)
{
    const float* x = (const float*)d_in[0];
    const float* w = (const float*)d_in[1];
    float* out = (float*)d_out;
    (void)in_sizes; (void)n_in; (void)out_size;

    cudaFuncSetAttribute(tp_fp16_kernel,
                         cudaFuncAttributeMaxDynamicSharedMemorySize, SMEM_TOTAL);

    convert_x_kernel<<<(TOKENS * (size_t)HIDDEN / 8 + 255) / 256, 256>>>(x);
    transpose_half_kernel<<<dim3(BLK / 32, BLK / 32, NB), dim3(32, 8)>>>(w);
    tp_fp16_kernel<<<dim3(TOKENS / BM, BLK / BN, NB), THREADS, SMEM_TOTAL>>>(out);
}